// round 10
// baseline (speedup 1.0000x reference)
#include <cuda_runtime.h>
#include <math.h>

// Problem constants
#define N_RES 2048
#define D_IN  128
#define T_SEQ 2048
#define GRID  128      // CTAs, all wave-1 resident (weights live in registers)
#define ROWS  16       // reservoir rows per CTA
#define NTH   544      // 16 worker warps (2 row-groups x 8 column-chunks) + 1 poller warp
#define PWARP 16       // poller warp id
#define SP_STRIDE 10   // sPart row stride (conflict-free finisher float2 reads)

// Scratch (allocation-free rule: __device__ globals)
__device__ float    g_U[(size_t)T_SEQ * N_RES];  // 16 MB: input @ W_in^T
__device__ unsigned g_flags[GRID * 32];          // per-CTA step flag, 128B stride

__global__ void esn_zero_kernel() {
    int i = blockIdx.x * blockDim.x + threadIdx.x;
    if (i < GRID * 32) g_flags[i] = 0u;
}

__device__ __forceinline__ unsigned ld_acq_gpu(const unsigned* p) {
    unsigned v;
    asm volatile("ld.acquire.gpu.global.u32 %0, [%1];" : "=r"(v) : "l"(p) : "memory");
    return v;
}
__device__ __forceinline__ void st_rel_gpu(unsigned* p, unsigned v) {
    asm volatile("st.release.gpu.global.u32 [%0], %1;" :: "l"(p), "r"(v) : "memory");
}
// SMEM relay: cta-scope acquire/release (generic addresses into __shared__)
__device__ __forceinline__ unsigned ld_acq_cta(const unsigned* p) {
    unsigned v;
    asm volatile("ld.acquire.cta.u32 %0, [%1];" : "=r"(v) : "l"(p) : "memory");
    return v;
}
__device__ __forceinline__ void st_rel_cta(unsigned* p, unsigned v) {
    asm volatile("st.release.cta.u32 [%0], %1;" :: "l"(p), "r"(v) : "memory");
}
__device__ __forceinline__ unsigned long long ffma2(unsigned long long a,
                                                    unsigned long long b,
                                                    unsigned long long c) {
    unsigned long long d;
    asm("fma.rn.f32x2 %0, %1, %2, %3;" : "=l"(d) : "l"(a), "l"(b), "l"(c));
    return d;
}
__device__ __forceinline__ float hadd2(unsigned long long a) {
    unsigned lo, hi;
    asm("mov.b64 {%0,%1}, %2;" : "=r"(lo), "=r"(hi) : "l"(a));
    return __uint_as_float(lo) + __uint_as_float(hi);
}
__device__ __forceinline__ void ldcg_v2u64(const void* p,
                                           unsigned long long& a, unsigned long long& b) {
    asm volatile("ld.global.cg.v2.u64 {%0,%1}, [%2];" : "=l"(a), "=l"(b) : "l"(p));
}

__global__ void __launch_bounds__(NTH, 1)
esn_kernel(const float* __restrict__ inp,    // (T, D_IN)
           const float* __restrict__ Win,    // (N_RES, D_IN)
           const float* __restrict__ Wres,   // (N_RES, N_RES)
           float*       __restrict__ out)    // (T, N_RES)
{
    __shared__ float    sWin[ROWS * D_IN];        // prologue only
    __shared__ float    sPart[ROWS * SP_STRIDE];  // [row][chunk] partials
    __shared__ unsigned sReady[8];                // per-chunk ready step (poller -> workers)

    const int tid  = threadIdx.x;
    const int bid  = blockIdx.x;
    const int row0 = bid * ROWS;
    const int warp = tid >> 5;
    const int lane = tid & 31;
    const int g    = warp & 1;                   // row-group: rows 8g..8g+7
    const int cch  = warp >> 1;                  // column-chunk: cols 256*cch..+255
    const int cb   = cch * 256 + lane * 8;       // this thread's 8-column base
    // lane -> row-within-group after the merged butterfly
    const int rsel = 4 * (lane & 1) + 2 * ((lane >> 1) & 1) + ((lane >> 2) & 1);

    if (tid < 8) sReady[tid] = 0u;

    // ---- stage W_in slice into SMEM ----
    for (int i = tid; i < ROWS * D_IN; i += NTH)
        sWin[i] = Win[(size_t)row0 * D_IN + i];
    __syncthreads();

    // ---- prologue: U[t][row0..row0+15] for all t ----
    for (int t = tid; t < T_SEQ; t += NTH) {
        float acc[ROWS];
        #pragma unroll
        for (int r = 0; r < ROWS; ++r) acc[r] = 0.f;
        #pragma unroll
        for (int c = 0; c < 4; ++c) {
            float4 xin[8];
            const float4* ip = (const float4*)(inp + (size_t)t * D_IN + c * 32);
            #pragma unroll
            for (int k = 0; k < 8; ++k) xin[k] = ip[k];
            #pragma unroll
            for (int r = 0; r < ROWS; ++r) {
                const float4* wr = (const float4*)(sWin + r * D_IN + c * 32);
                #pragma unroll
                for (int k = 0; k < 8; ++k) {
                    float4 w = wr[k];
                    acc[r] += w.x * xin[k].x + w.y * xin[k].y
                            + w.z * xin[k].z + w.w * xin[k].w;
                }
            }
        }
        #pragma unroll
        for (int r = 0; r < ROWS; ++r)
            g_U[(size_t)t * N_RES + row0 + r] = acc[r];
    }

    // ---- worker warps: W_res tile into registers (8 rows x 8 cols / lane) ----
    unsigned long long wv[8][4];
    if (warp < PWARP) {
        #pragma unroll
        for (int j = 0; j < 8; ++j) {
            const float* wr = Wres + (size_t)(row0 + 8 * g + j) * N_RES + cb;
            ulonglong2 q0 = *(const ulonglong2*)(wr);
            ulonglong2 q1 = *(const ulonglong2*)(wr + 4);
            wv[j][0] = q0.x; wv[j][1] = q0.y; wv[j][2] = q1.x; wv[j][3] = q1.y;
        }
    }
    __syncthreads();   // g_U + sReady init visible CTA-wide

    const float cns = 0.022097086912079612f;  // 1/sqrt(2048)

    if (warp == PWARP) {
        // ================= POLLER WARP =================
        // lane l owns flags of CTAs 4l..4l+3; lanes 0..7 publish chunks 0..7
        const unsigned* f0 = &g_flags[(4 * lane + 0) << 5];
        const unsigned* f1 = &g_flags[(4 * lane + 1) << 5];
        const unsigned* f2 = &g_flags[(4 * lane + 2) << 5];
        const unsigned* f3 = &g_flags[(4 * lane + 3) << 5];
        for (int t = 0; t < T_SEQ; ++t) {
            if (t > 0) {
                unsigned ballot;
                do {
                    unsigned a = ld_acq_gpu(f0), b = ld_acq_gpu(f1);
                    unsigned c = ld_acq_gpu(f2), d = ld_acq_gpu(f3);
                    bool ok4 = (a >= (unsigned)t) & (b >= (unsigned)t) &
                               (c >= (unsigned)t) & (d >= (unsigned)t);
                    ballot = __ballot_sync(0xffffffffu, ok4);
                    // publish any chunk whose 4 poll-lanes are all ready
                    if (lane < 8 && ((ballot >> (4 * lane)) & 0xFu) == 0xFu)
                        st_rel_cta(&sReady[lane], (unsigned)t);
                } while (ballot != 0xffffffffu);
            }
            __syncthreads();   // barrier (b)
        }
    } else {
        // ================= WORKER WARPS =================
        for (int t = 0; t < T_SEQ; ++t) {
            float uval = 0.f;
            if (warp == 0 && lane < ROWS)
                uval = __ldcg(g_U + (size_t)t * N_RES + row0 + lane);  // prefetch

            if (t > 0) {
                // fast SMEM spin: poller publishes this chunk's readiness
                while (ld_acq_cta(&sReady[cch]) < (unsigned)t) { }

                // this thread's 8 x-values (L2 path, 2x LDG.128)
                unsigned long long x0, x1, x2, x3;
                const float* xp = out + (size_t)(t - 1) * N_RES + cb;
                ldcg_v2u64(xp,     x0, x1);
                ldcg_v2u64(xp + 4, x2, x3);

                // 8 rows x 4 packed FMAs
                float p[8];
                #pragma unroll
                for (int j = 0; j < 8; ++j) {
                    unsigned long long a = ffma2(wv[j][0], x0, 0ull);
                    unsigned long long b = ffma2(wv[j][1], x1, 0ull);
                    a = ffma2(wv[j][2], x2, a);
                    b = ffma2(wv[j][3], x3, b);
                    p[j] = hadd2(a) + hadd2(b);
                }

                // merged butterfly: 8 row-sums across 32 lanes in 9 SHFLs
                #pragma unroll
                for (int j = 0; j < 4; ++j) {
                    float send = (lane & 1) ? p[j] : p[j + 4];
                    float recv = __shfl_xor_sync(0xffffffffu, send, 1);
                    p[j] = ((lane & 1) ? p[j + 4] : p[j]) + recv;
                }
                #pragma unroll
                for (int j = 0; j < 2; ++j) {
                    float send = (lane & 2) ? p[j] : p[j + 2];
                    float recv = __shfl_xor_sync(0xffffffffu, send, 2);
                    p[j] = ((lane & 2) ? p[j + 2] : p[j]) + recv;
                }
                {
                    float send = (lane & 4) ? p[0] : p[1];
                    float recv = __shfl_xor_sync(0xffffffffu, send, 4);
                    p[0] = ((lane & 4) ? p[1] : p[0]) + recv;
                }
                p[0] += __shfl_xor_sync(0xffffffffu, p[0], 8);
                p[0] += __shfl_xor_sync(0xffffffffu, p[0], 16);

                if (lane < 8)
                    sPart[(8 * g + rsel) * SP_STRIDE + cch] = p[0];
            }
            __syncthreads();   // barrier (b): partials ready

            // finishers: warp 0 lanes 0..15 (one row each); no barrier (c)
            if (warp == 0) {
                if (lane < ROWS) {
                    float pre = uval;
                    if (t > 0) {
                        const float2* pp = (const float2*)(sPart + lane * SP_STRIDE);
                        float2 a0 = pp[0], a1 = pp[1], a2 = pp[2], a3 = pp[3];
                        pre += ((a0.x + a0.y) + (a1.x + a1.y))
                             + ((a2.x + a2.y) + (a3.x + a3.y));
                    }
                    __stcg(out + (size_t)t * N_RES + row0 + lane, erff(pre) * cns);
                }
                __syncwarp();
                if (lane == 0) st_rel_gpu(&g_flags[bid << 5], (unsigned)(t + 1));
            }
            // other warps fall through to the next step's SMEM spin immediately;
            // sPart reuse is safe: finisher reads precede the next barrier (b)
            // because warp 0 writes sPart only after its own next-step spin+compute,
            // which follows its finisher reads program-order-wise.
        }
    }
}

extern "C" void kernel_launch(void* const* d_in, const int* in_sizes, int n_in,
                              void* d_out, int out_size) {
    const float* inp  = (const float*)d_in[0];   // input_data (2048,128)
    const float* Win  = (const float*)d_in[1];   // W_in       (2048,128)
    const float* Wres = (const float*)d_in[2];   // W_res      (2048,2048)
    float* out = (float*)d_out;                  // (2048,2048) float32

    esn_zero_kernel<<<4, 1024>>>();
    esn_kernel<<<GRID, NTH>>>(inp, Win, Wres, out);
}